// round 10
// baseline (speedup 1.0000x reference)
#include <cuda_runtime.h>
#include <cuda_fp16.h>
#include <cstdint>

// Problem constants
#define N_TOK 16384
#define C_DIM 2048
#define E_DIM 64
#define CAP   640                 // int(1.25 * 16384 * 2 / 64)

#define TOK_CTA   128             // tokens per k_main CTA
#define NCTA_MAIN (N_TOK / TOK_CTA)   // 128
#define KT        32              // K-tile (2 x k16 mma steps)
#define NTILE     (C_DIM / KT)    // 64
#define NBLK64    256             // 64-token blocks (rank/scan granularity)

#define XSTR 40                   // xs row stride (floats)
#define BSTR 40                   // W tile row stride (halves)
#define GSTR 66                   // logits row stride (floats)

#define XS_BYTES (TOK_CTA * XSTR * 4)     // 20480
#define WH_BYTES (E_DIM * BSTR * 2)       // 5120
#define STAGE_B  (XS_BYTES + 2 * WH_BYTES)    // 30720
#define NSTAGE   3
#define SMEM_DYN (NSTAGE * STAGE_B)           // 92160

#define INV1024 0.0009765625f

// Output layout (float32)
#define DISP_OFF  ((size_t)0)
#define COMB_OFF  ((size_t)N_TOK * E_DIM * 2)
#define AUX_OFF   ((size_t)2 * N_TOK * E_DIM * 2)
#define Z_OFF     (AUX_OFF + 1)

// ---------------- scratch (static device globals; no allocs) ----------------
__device__ __half   g_Whh[E_DIM * C_DIM];   // fp16 hi part of W [e][k]
__device__ __half   g_Whl[E_DIM * C_DIM];   // fp16 (lo part * 1024)
__device__ uint32_t g_t2i[N_TOK];           // e1 | e2<<8
__device__ float2   g_t2v[N_TOK];           // top2 gate values
__device__ uint32_t g_rank[N_TOK];          // local rank: r0 | r1<<16
__device__ int      g_counts[NBLK64 * 128]; // per-64tok-block bin counts
__device__ int      g_off[NBLK64 * 128];    // exclusive scan across blocks
__device__ float    g_mepart[NCTA_MAIN * E_DIM];
__device__ float    g_zpart[NCTA_MAIN];
__device__ int      g_ctr;                  // last-CTA counter (reset each launch)

// ---------------- helpers ----------------
__device__ __forceinline__ uint32_t smem_u32(const void* p) {
    return (uint32_t)__cvta_generic_to_shared(p);
}
__device__ __forceinline__ void cpa16(uint32_t dst, const void* src) {
    asm volatile("cp.async.cg.shared.global [%0], [%1], 16;"
                 :: "r"(dst), "l"(src) : "memory");
}
__device__ __forceinline__ void mma16(float* d,
                                      uint32_t a0, uint32_t a1, uint32_t a2, uint32_t a3,
                                      uint32_t b0, uint32_t b1) {
    asm volatile(
        "mma.sync.aligned.m16n8k16.row.col.f32.f16.f16.f32 "
        "{%0,%1,%2,%3}, {%4,%5,%6,%7}, {%8,%9}, {%0,%1,%2,%3};"
        : "+f"(d[0]), "+f"(d[1]), "+f"(d[2]), "+f"(d[3])
        : "r"(a0), "r"(a1), "r"(a2), "r"(a3), "r"(b0), "r"(b1));
}
__device__ __forceinline__ void split2(float2 v, uint32_t& h, uint32_t& l) {
    __half2 hh = __floats2half2_rn(v.x, v.y);
    float2 hf = __half22float2(hh);
    __half2 ll = __floats2half2_rn(v.x - hf.x, v.y - hf.y);
    h = *(uint32_t*)&hh;
    l = *(uint32_t*)&ll;
}

// ---------------- K0: split W into fp16 hi / (lo*1024) ----------------
__global__ __launch_bounds__(256) void k_wsplit(const float* __restrict__ W) {
    int idx = blockIdx.x * 256 + threadIdx.x;   // 131072
    float v = W[idx];
    __half h = __float2half_rn(v);
    g_Whh[idx] = h;
    g_Whl[idx] = __float2half_rn((v - __half2float(h)) * 1024.0f);
}

// ---------------- K1: mma.sync fp16-split GEMM + epilogue + fused scan -----
// 256 threads (8 warps). Warp w: tokens [w*16, w*16+16), all 64 experts.
// 8 n-tiles of m16n8k16; accM = (xh+xl)*wh, accL = xh*(wl*1024).
// 3-stage cp.async ring, one __syncthreads per tile.
// Last CTA (atomic counter) performs the cross-block scan + losses.
__global__ __launch_bounds__(256) void k_main(const float* __restrict__ x,
                                              float* __restrict__ out) {
    extern __shared__ __align__(16) char smc[];
    __shared__ int   cnt[512];          // [half][warp_in_half][128 bins]
    __shared__ float sinv_s[TOK_CTA];
    __shared__ float redz[4];
    __shared__ float fred[256];
    __shared__ int   hsum[2][128];
    __shared__ int   s_last;

    const int tid  = threadIdx.x;
    const int lane = tid & 31;
    const int w    = tid >> 5;
    const int cta  = blockIdx.x;
    const uint32_t smb = smem_u32(smc);
    const float* xbase = x + (size_t)cta * TOK_CTA * C_DIM;

#define LOAD_TILE(t, stg) do {                                                \
    uint32_t sb_ = smb + (uint32_t)(stg) * STAGE_B;                           \
    const float* xs_ = xbase + (t) * KT;                                      \
    _Pragma("unroll")                                                         \
    for (int c = tid; c < 1024; c += 256) {                                   \
        int row_ = c >> 3, seg_ = c & 7;                                      \
        cpa16(sb_ + (uint32_t)(row_ * (XSTR * 4) + seg_ * 16),                \
              xs_ + (size_t)row_ * C_DIM + seg_ * 4);                         \
    }                                                                         \
    {                                                                         \
        int row_ = tid >> 2, seg_ = tid & 3;                                  \
        const __half* wh_ = g_Whh + (size_t)row_ * C_DIM + (t) * KT + seg_ * 8;\
        const __half* wl_ = g_Whl + (size_t)row_ * C_DIM + (t) * KT + seg_ * 8;\
        cpa16(sb_ + XS_BYTES + (uint32_t)(row_ * (BSTR * 2) + seg_ * 16), wh_);\
        cpa16(sb_ + XS_BYTES + WH_BYTES + (uint32_t)(row_ * (BSTR * 2) + seg_ * 16), wl_);\
    }                                                                         \
} while (0)

    float accM[8][4], accL[8][4];
#pragma unroll
    for (int j = 0; j < 8; j++)
#pragma unroll
        for (int q = 0; q < 4; q++) { accM[j][q] = 0.f; accL[j][q] = 0.f; }

    const int tb = w * 16;
    const int tr = lane >> 2, tc = lane & 3;

    LOAD_TILE(0, 0);
    asm volatile("cp.async.commit_group;" ::: "memory");
    LOAD_TILE(1, 1);
    asm volatile("cp.async.commit_group;" ::: "memory");

    int stg = 0;          // stage of tile t
    for (int t = 0; t < NTILE; t++) {
        asm volatile("cp.async.wait_group 1;" ::: "memory");
        __syncthreads();

        // prefetch t+2 into stage (t+2)%3 == (stg+2)%3 — not read this iter
        int pstg = stg + 2; if (pstg >= NSTAGE) pstg -= NSTAGE;
        if (t + 2 < NTILE) LOAD_TILE(t + 2, pstg);
        asm volatile("cp.async.commit_group;" ::: "memory");

        const char* st = smc + stg * STAGE_B;
        const float* xsA = (const float*)st + (tb + tr) * XSTR + 2 * tc;
        const __half* whB = (const __half*)(st + XS_BYTES) + tr * BSTR + 2 * tc;
        const __half* wlB = (const __half*)(st + XS_BYTES + WH_BYTES) + tr * BSTR + 2 * tc;

#pragma unroll
        for (int kk = 0; kk < KT; kk += 16) {
            float2 v0 = *(const float2*)(xsA + kk);
            float2 v1 = *(const float2*)(xsA + 8 * XSTR + kk);
            float2 v2 = *(const float2*)(xsA + kk + 8);
            float2 v3 = *(const float2*)(xsA + 8 * XSTR + kk + 8);
            uint32_t ah0, al0, ah1, al1, ah2, al2, ah3, al3;
            split2(v0, ah0, al0);
            split2(v1, ah1, al1);
            split2(v2, ah2, al2);
            split2(v3, ah3, al3);

#pragma unroll
            for (int j = 0; j < 8; j++) {
                const __half* whj = whB + j * 8 * BSTR + kk;
                const __half* wlj = wlB + j * 8 * BSTR + kk;
                uint32_t bh0 = *(const uint32_t*)whj;
                uint32_t bh1 = *(const uint32_t*)(whj + 8);
                uint32_t bl0 = *(const uint32_t*)wlj;
                uint32_t bl1 = *(const uint32_t*)(wlj + 8);
                mma16(accM[j], ah0, ah1, ah2, ah3, bh0, bh1);
                mma16(accM[j], al0, al1, al2, al3, bh0, bh1);
                mma16(accL[j], ah0, ah1, ah2, ah3, bl0, bl1);
            }
        }
        stg++; if (stg >= NSTAGE) stg -= NSTAGE;
    }

    // ---- combine + store logits to smem (stage0 reuse), stride GSTR ----
    float* gsm = (float*)smc;
    __syncthreads();
#pragma unroll
    for (int j = 0; j < 8; j++) {
        float l0 = accM[j][0] + accL[j][0] * INV1024;
        float l1 = accM[j][1] + accL[j][1] * INV1024;
        float l2 = accM[j][2] + accL[j][2] * INV1024;
        float l3 = accM[j][3] + accL[j][3] * INV1024;
        *(float2*)(gsm + (tb + tr) * GSTR + j * 8 + tc * 2) = make_float2(l0, l1);
        *(float2*)(gsm + (tb + tr + 8) * GSTR + j * 8 + tc * 2) = make_float2(l2, l3);
    }
    cnt[tid] = 0;
    cnt[tid + 256] = 0;
    __syncthreads();

    // ---- per-token softmax + top2 (threads 0..127, one token each) ----
    int i1 = 0, i2 = 0, r0 = 0, r1 = 0;
    float zsum = 0.f;
    if (w < 4) {
        float* row = gsm + tid * GSTR;
        float m = row[0];
#pragma unroll 4
        for (int e = 1; e < E_DIM; e++) m = fmaxf(m, row[e]);
        float s = 0.f, b1 = -1.f, b2 = -1.f;
#pragma unroll 4
        for (int e = 0; e < E_DIM; e++) {
            float l = row[e];
            zsum += l * l;
            float v = expf(l - m);
            row[e] = v;            // overwrite with unnormalized gate
            s += v;
            if (v > b1)      { b2 = b1; i2 = i1; b1 = v; i1 = e; }
            else if (v > b2) { b2 = v; i2 = e; }
        }
        float sinv = 1.f / s;
        sinv_s[tid] = sinv;
        int n = cta * TOK_CTA + tid;
        g_t2v[n] = make_float2(b1 * sinv, b2 * sinv);

        // deterministic local ranks (token order) within each 64-token half
        int half = w >> 1, wih = w & 1;
        unsigned lt = (1u << lane) - 1u;
        unsigned m0 = __match_any_sync(0xffffffffu, i1);
        r0 = __popc(m0 & lt);
        if ((m0 & lt) == 0) cnt[half * 256 + wih * 128 + i1] = __popc(m0);
        unsigned m1 = __match_any_sync(0xffffffffu, i2);
        r1 = __popc(m1 & lt);
        if ((m1 & lt) == 0) cnt[half * 256 + wih * 128 + 64 + i2] = __popc(m1);
    }
    // z reduce (warps 4..7 contribute zeros)
#pragma unroll
    for (int o = 16; o > 0; o >>= 1) zsum += __shfl_xor_sync(0xffffffffu, zsum, o);
    if (w < 4 && lane == 0) redz[w] = zsum;
    __syncthreads();

    if (w < 4) {
        int half = w >> 1;
        if ((w & 1) == 1) {               // second warp of half adds first warp's counts
            r0 += cnt[half * 256 + i1];
            r1 += cnt[half * 256 + 64 + i2];
        }
        int n = cta * TOK_CTA + tid;
        g_rank[n] = (uint32_t)r0 | ((uint32_t)r1 << 16);
        g_t2i[n]  = (uint32_t)i1 | ((uint32_t)i2 << 8);
    }
    {   // per-64tok-block bin counts (tid covers 256 = 2 halves x 128 bins)
        int half = tid >> 7, b = tid & 127;
        g_counts[(cta * 2 + half) * 128 + b] =
            cnt[half * 256 + b] + cnt[half * 256 + 128 + b];
    }
    if (tid < 64) {
        float sme = 0.f;
        for (int tok = 0; tok < TOK_CTA; tok++)
            sme += gsm[tok * GSTR + tid] * sinv_s[tok];
        g_mepart[cta * 64 + tid] = sme;
    }
    if (tid == 0)
        g_zpart[cta] = redz[0] + redz[1] + redz[2] + redz[3];

    // ================= last-CTA fused scan + losses =================
    __threadfence();
    if (tid == 0) s_last = (atomicAdd(&g_ctr, 1) == NCTA_MAIN - 1) ? 1 : 0;
    __syncthreads();
    if (!s_last) return;
    __threadfence();                      // acquire all CTAs' writes
    if (tid == 0) g_ctr = 0;              // reset for next launch (determinism)

    {   // exclusive scan over 256 blocks per bin; thread = (half, bin)
        int b = tid & 127, half = tid >> 7;
        int run = 0;
        int base = half * 128;
        for (int blk = base; blk < base + 128; blk++) {
            int c = g_counts[blk * 128 + b];
            g_off[blk * 128 + b] = run;
            run += c;
        }
        hsum[half][b] = run;
        __syncthreads();
        if (half == 1) {
            int add = hsum[0][b];
            for (int blk = 128; blk < 256; blk++)
                g_off[blk * 128 + b] += add;
        }
    }
    __syncthreads();

    // losses
    {
        int e = tid >> 2, q = tid & 3;
        float msum = 0.f;
        for (int blk = q * 32; blk < q * 32 + 32; blk++)
            msum += g_mepart[blk * 64 + e];
        fred[tid] = msum;
    }
    __syncthreads();
    float a = 0.f;
    if (tid < 64) {
        float me = (fred[4*tid] + fred[4*tid+1] + fred[4*tid+2] + fred[4*tid+3])
                   * (1.f / (float)N_TOK);
        float ce = (float)(hsum[0][tid] + hsum[1][tid]) * (1.f / (float)N_TOK);
        a = (float)E_DIM * me * ce;       // top-1 bins are 0..63
    }
    __syncthreads();
    fred[tid] = (tid < 64) ? a : 0.f;
    __syncthreads();
    for (int s = 128; s > 0; s >>= 1) {
        if (tid < s) fred[tid] += fred[tid + s];
        __syncthreads();
    }
    if (tid == 0) out[AUX_OFF] = fred[0];
    __syncthreads();

    fred[tid] = (tid < NCTA_MAIN) ? g_zpart[tid] : 0.f;
    __syncthreads();
    for (int s = 128; s > 0; s >>= 1) {
        if (tid < s) fred[tid] += fred[tid + s];
        __syncthreads();
    }
    if (tid == 0) out[Z_OFF] = fred[0] * (1.f / ((float)N_TOK * (float)E_DIM));
#undef LOAD_TILE
}

// ---------------- K3: dense per-token writes (no zero pass, no sync) -------
// 2048 CTAs x 256 threads; warp per token; lane owns experts 2*lane, 2*lane+1.
__global__ __launch_bounds__(256) void k_out(float* __restrict__ out) {
    const int n    = (blockIdx.x << 3) + (threadIdx.x >> 5);  // token 0..16383
    const int lane = threadIdx.x & 31;

    uint32_t ii = g_t2i[n];
    int e1 = ii & 0xff, e2 = (ii >> 8) & 0xff;
    uint32_t rr = g_rank[n];
    float2 vv = g_t2v[n];
    int blk64 = n >> 6;

    int pos0 = g_off[blk64 * 128 + e1]      + (int)(rr & 0xffff);
    int pos1 = g_off[blk64 * 128 + 64 + e2] + (int)(rr >> 16);
    bool k0 = pos0 < CAP, k1 = pos1 < CAP;

    int ea = 2 * lane, ebx = 2 * lane + 1;
    float4 d = make_float4(0.f, 0.f, 0.f, 0.f);
    float4 c = make_float4(0.f, 0.f, 0.f, 0.f);
    if (k0 && e1 == ea)  { d.x = 1.f; c.x = vv.x; }
    if (k1 && e2 == ea)  { d.y = 1.f; c.y = vv.y; }
    if (k0 && e1 == ebx) { d.z = 1.f; c.z = vv.x; }
    if (k1 && e2 == ebx) { d.w = 1.f; c.w = vv.y; }

    size_t base = (size_t)n * 128 + lane * 4;
    *(float4*)(out + DISP_OFF + base) = d;
    *(float4*)(out + COMB_OFF + base) = c;
}

// ---------------- entry ----------------
extern "C" void kernel_launch(void* const* d_in, const int* in_sizes, int n_in,
                              void* d_out, int out_size) {
    const float* x = (const float*)d_in[0];   // [16384, 2048]
    const float* W = (const float*)d_in[1];   // [64, 2048]
    float* out = (float*)d_out;

    cudaFuncSetAttribute(k_main, cudaFuncAttributeMaxDynamicSharedMemorySize, SMEM_DYN);

    k_wsplit<<<(E_DIM * C_DIM) / 256, 256>>>(W);
    k_main<<<NCTA_MAIN, 256, SMEM_DYN>>>(x, out);
    k_out<<<N_TOK / 8, 256>>>(out);
}

// round 15
// speedup vs baseline: 1.0735x; 1.0735x over previous
#include <cuda_runtime.h>
#include <cuda_fp16.h>
#include <cstdint>

// Problem constants
#define N_TOK 16384
#define C_DIM 2048
#define E_DIM 64
#define CAP   640                 // int(1.25 * 16384 * 2 / 64)

#define TOK_CTA   128             // tokens per k_main CTA
#define NCTA_MAIN (N_TOK / TOK_CTA)   // 128
#define KT        32              // K-tile (2 x k16 mma steps)
#define NTILE     (C_DIM / KT)    // 64
#define NBLK64    256             // 64-token blocks (rank/scan granularity)

#define XSTR 40                   // xs row stride (floats)
#define BSTR 40                   // W tile row stride (halves)
#define GSTR 66                   // logits row stride (floats)

#define XS_BYTES (TOK_CTA * XSTR * 4)     // 20480
#define WH_BYTES (E_DIM * BSTR * 2)       // 5120
#define STAGE_B  (XS_BYTES + 2 * WH_BYTES)    // 30720
#define SMEM_DYN (2 * STAGE_B)                // 61440

#define INV1024 0.0009765625f

// Output layout (float32)
#define DISP_OFF  ((size_t)0)
#define COMB_OFF  ((size_t)N_TOK * E_DIM * 2)
#define AUX_OFF   ((size_t)2 * N_TOK * E_DIM * 2)
#define Z_OFF     (AUX_OFF + 1)

// ---------------- scratch (static device globals; no allocs) ----------------
__device__ __half   g_Whh[E_DIM * C_DIM];   // fp16 hi part of W [e][k]
__device__ __half   g_Whl[E_DIM * C_DIM];   // fp16 (lo part * 1024)
__device__ uint32_t g_t2i[N_TOK];           // e1 | e2<<8
__device__ float2   g_t2v[N_TOK];           // top2 gate values
__device__ uint32_t g_rank[N_TOK];          // local rank: r0 | r1<<16
__device__ int      g_counts[NBLK64 * 128]; // per-64tok-block bin counts
__device__ int      g_off[NBLK64 * 128];    // exclusive scan across blocks
__device__ float    g_mepart[NCTA_MAIN * E_DIM];
__device__ float    g_zpart[NCTA_MAIN];

// ---------------- helpers ----------------
__device__ __forceinline__ uint32_t smem_u32(const void* p) {
    return (uint32_t)__cvta_generic_to_shared(p);
}
__device__ __forceinline__ void cpa16(uint32_t dst, const void* src) {
    asm volatile("cp.async.cg.shared.global [%0], [%1], 16;"
                 :: "r"(dst), "l"(src) : "memory");
}
__device__ __forceinline__ void mma16(float* d,
                                      uint32_t a0, uint32_t a1, uint32_t a2, uint32_t a3,
                                      uint32_t b0, uint32_t b1) {
    asm volatile(
        "mma.sync.aligned.m16n8k16.row.col.f32.f16.f16.f32 "
        "{%0,%1,%2,%3}, {%4,%5,%6,%7}, {%8,%9}, {%0,%1,%2,%3};"
        : "+f"(d[0]), "+f"(d[1]), "+f"(d[2]), "+f"(d[3])
        : "r"(a0), "r"(a1), "r"(a2), "r"(a3), "r"(b0), "r"(b1));
}
__device__ __forceinline__ void split2(float2 v, uint32_t& h, uint32_t& l) {
    __half2 hh = __floats2half2_rn(v.x, v.y);
    float2 hf = __half22float2(hh);
    __half2 ll = __floats2half2_rn(v.x - hf.x, v.y - hf.y);
    h = *(uint32_t*)&hh;
    l = *(uint32_t*)&ll;
}

// ---------------- K0: split W into fp16 hi / (lo*1024), vectorized ---------
// 64 CTAs x 256 threads; each thread handles 2 float4s (512 float4 per CTA).
__global__ __launch_bounds__(256) void k_wsplit(const float* __restrict__ W) {
    int base = blockIdx.x * 512 + threadIdx.x;   // float4 index space (32768)
    const float4* W4 = (const float4*)W;
    uint2* H2 = (uint2*)g_Whh;
    uint2* L2 = (uint2*)g_Whl;
#pragma unroll
    for (int r = 0; r < 2; r++) {
        int i = base + r * 256;
        float4 v = W4[i];
        __half2 h0 = __floats2half2_rn(v.x, v.y);
        __half2 h1 = __floats2half2_rn(v.z, v.w);
        float2 f0 = __half22float2(h0);
        float2 f1 = __half22float2(h1);
        __half2 l0 = __floats2half2_rn((v.x - f0.x) * 1024.f, (v.y - f0.y) * 1024.f);
        __half2 l1 = __floats2half2_rn((v.z - f1.x) * 1024.f, (v.w - f1.y) * 1024.f);
        H2[i] = make_uint2(*(uint32_t*)&h0, *(uint32_t*)&h1);
        L2[i] = make_uint2(*(uint32_t*)&l0, *(uint32_t*)&l1);
    }
}

// ---------------- K1: mma.sync fp16-split GEMM + softmax + top2 + ranks ----
// 256 threads (8 warps). Warp w: tokens [w*16, w*16+16), all 64 experts.
// 8 n-tiles of m16n8k16; accM = (xh+xl)*wh, accL = xh*(wl*1024).
// Also zeroes this CTA's output slice from inside the loop (idle store pipe).
__global__ __launch_bounds__(256) void k_main(const float* __restrict__ x,
                                              float* __restrict__ out) {
    extern __shared__ __align__(16) char smc[];
    __shared__ int   cnt[512];          // [half][warp_in_half][128 bins]
    __shared__ float sinv_s[TOK_CTA];
    __shared__ float redz[4];

    const int tid  = threadIdx.x;
    const int lane = tid & 31;
    const int w    = tid >> 5;
    const int cta  = blockIdx.x;
    const uint32_t smb = smem_u32(smc);
    const float* xbase = x + (size_t)cta * TOK_CTA * C_DIM;

    float4* zd = (float4*)(out + DISP_OFF + (size_t)cta * TOK_CTA * 128);
    float4* zc = (float4*)(out + COMB_OFF + (size_t)cta * TOK_CTA * 128);

#define LOAD_TILE(t) do {                                                     \
    uint32_t sb_ = smb + ((t) & 1) * STAGE_B;                                 \
    const float* xs_ = xbase + (t) * KT;                                      \
    _Pragma("unroll")                                                         \
    for (int c = tid; c < 1024; c += 256) {                                   \
        int row_ = c >> 3, seg_ = c & 7;                                      \
        cpa16(sb_ + (uint32_t)(row_ * (XSTR * 4) + seg_ * 16),                \
              xs_ + (size_t)row_ * C_DIM + seg_ * 4);                         \
    }                                                                         \
    {                                                                         \
        int row_ = tid >> 2, seg_ = tid & 3;                                  \
        const __half* wh_ = g_Whh + (size_t)row_ * C_DIM + (t) * KT + seg_ * 8;\
        const __half* wl_ = g_Whl + (size_t)row_ * C_DIM + (t) * KT + seg_ * 8;\
        cpa16(sb_ + XS_BYTES + (uint32_t)(row_ * (BSTR * 2) + seg_ * 16), wh_);\
        cpa16(sb_ + XS_BYTES + WH_BYTES + (uint32_t)(row_ * (BSTR * 2) + seg_ * 16), wl_);\
    }                                                                         \
} while (0)

    float accM[8][4], accL[8][4];
#pragma unroll
    for (int j = 0; j < 8; j++)
#pragma unroll
        for (int q = 0; q < 4; q++) { accM[j][q] = 0.f; accL[j][q] = 0.f; }

    const int tb = w * 16;
    const int tr = lane >> 2, tc = lane & 3;

    LOAD_TILE(0);
    asm volatile("cp.async.commit_group;" ::: "memory");

    for (int t = 0; t < NTILE; t++) {
        if (t + 1 < NTILE) LOAD_TILE(t + 1);
        asm volatile("cp.async.commit_group;" ::: "memory");
        asm volatile("cp.async.wait_group 1;" ::: "memory");
        __syncthreads();

        const char* st = smc + (t & 1) * STAGE_B;
        const float* xsA = (const float*)st + (tb + tr) * XSTR + 2 * tc;
        const __half* whB = (const __half*)(st + XS_BYTES) + tr * BSTR + 2 * tc;
        const __half* wlB = (const __half*)(st + XS_BYTES + WH_BYTES) + tr * BSTR + 2 * tc;

#pragma unroll
        for (int kk = 0; kk < KT; kk += 16) {
            float2 v0 = *(const float2*)(xsA + kk);
            float2 v1 = *(const float2*)(xsA + 8 * XSTR + kk);
            float2 v2 = *(const float2*)(xsA + kk + 8);
            float2 v3 = *(const float2*)(xsA + 8 * XSTR + kk + 8);
            uint32_t ah0, al0, ah1, al1, ah2, al2, ah3, al3;
            split2(v0, ah0, al0);
            split2(v1, ah1, al1);
            split2(v2, ah2, al2);
            split2(v3, ah3, al3);

#pragma unroll
            for (int j = 0; j < 8; j++) {
                const __half* whj = whB + j * 8 * BSTR + kk;
                const __half* wlj = wlB + j * 8 * BSTR + kk;
                uint32_t bh0 = *(const uint32_t*)whj;
                uint32_t bh1 = *(const uint32_t*)(whj + 8);
                uint32_t bl0 = *(const uint32_t*)wlj;
                uint32_t bl1 = *(const uint32_t*)(wlj + 8);
                mma16(accM[j], ah0, ah1, ah2, ah3, bh0, bh1);
                mma16(accM[j], al0, al1, al2, al3, bh0, bh1);
                mma16(accL[j], ah0, ah1, ah2, ah3, bl0, bl1);
            }
        }

        // zero this CTA's output slice using the idle store pipe
        if (t < 16) {
            float4 z4 = make_float4(0.f, 0.f, 0.f, 0.f);
            zd[t * 256 + tid] = z4;
            zc[t * 256 + tid] = z4;
        }
        __syncthreads();   // protect buffer t&1 before iter t+1 prefetches t+2
    }

    // ---- combine + store logits to smem (stage0 reuse), stride GSTR ----
    float* gsm = (float*)smc;
    __syncthreads();
#pragma unroll
    for (int j = 0; j < 8; j++) {
        float l0 = accM[j][0] + accL[j][0] * INV1024;
        float l1 = accM[j][1] + accL[j][1] * INV1024;
        float l2 = accM[j][2] + accL[j][2] * INV1024;
        float l3 = accM[j][3] + accL[j][3] * INV1024;
        *(float2*)(gsm + (tb + tr) * GSTR + j * 8 + tc * 2) = make_float2(l0, l1);
        *(float2*)(gsm + (tb + tr + 8) * GSTR + j * 8 + tc * 2) = make_float2(l2, l3);
    }
    cnt[tid] = 0;
    cnt[tid + 256] = 0;
    __syncthreads();

    // ---- per-token softmax + top2 (threads 0..127, one token each) ----
    int i1 = 0, i2 = 0, r0 = 0, r1 = 0;
    float zsum = 0.f;
    if (w < 4) {
        float* row = gsm + tid * GSTR;
        float m = row[0];
#pragma unroll 4
        for (int e = 1; e < E_DIM; e++) m = fmaxf(m, row[e]);
        float s = 0.f, b1 = -1.f, b2 = -1.f;
#pragma unroll 4
        for (int e = 0; e < E_DIM; e++) {
            float l = row[e];
            zsum += l * l;
            float v = expf(l - m);
            row[e] = v;            // overwrite with unnormalized gate
            s += v;
            if (v > b1)      { b2 = b1; i2 = i1; b1 = v; i1 = e; }
            else if (v > b2) { b2 = v; i2 = e; }
        }
        float sinv = 1.f / s;
        sinv_s[tid] = sinv;
        int n = cta * TOK_CTA + tid;
        g_t2v[n] = make_float2(b1 * sinv, b2 * sinv);

        // deterministic local ranks (token order) within each 64-token half
        int half = w >> 1, wih = w & 1;
        unsigned lt = (1u << lane) - 1u;
        unsigned m0 = __match_any_sync(0xffffffffu, i1);
        r0 = __popc(m0 & lt);
        if ((m0 & lt) == 0) cnt[half * 256 + wih * 128 + i1] = __popc(m0);
        unsigned m1 = __match_any_sync(0xffffffffu, i2);
        r1 = __popc(m1 & lt);
        if ((m1 & lt) == 0) cnt[half * 256 + wih * 128 + 64 + i2] = __popc(m1);
    }
    // z reduce (warps 4..7 contribute zeros)
#pragma unroll
    for (int o = 16; o > 0; o >>= 1) zsum += __shfl_xor_sync(0xffffffffu, zsum, o);
    if (w < 4 && lane == 0) redz[w] = zsum;
    __syncthreads();

    if (w < 4) {
        int half = w >> 1;
        if ((w & 1) == 1) {               // second warp of half adds first warp's counts
            r0 += cnt[half * 256 + i1];
            r1 += cnt[half * 256 + 64 + i2];
        }
        int n = cta * TOK_CTA + tid;
        g_rank[n] = (uint32_t)r0 | ((uint32_t)r1 << 16);
        g_t2i[n]  = (uint32_t)i1 | ((uint32_t)i2 << 8);
    }
    {   // per-64tok-block bin counts (tid covers 256 = 2 halves x 128 bins)
        int half = tid >> 7, b = tid & 127;
        g_counts[(cta * 2 + half) * 128 + b] =
            cnt[half * 256 + b] + cnt[half * 256 + 128 + b];
    }
    if (tid < 64) {
        float sme = 0.f;
        for (int tok = 0; tok < TOK_CTA; tok++)
            sme += gsm[tok * GSTR + tid] * sinv_s[tok];
        g_mepart[cta * 64 + tid] = sme;
    }
    if (tid == 0)
        g_zpart[cta] = redz[0] + redz[1] + redz[2] + redz[3];
#undef LOAD_TILE
}

// ---------------- K2: per-bin scan (blocks 0..127) + losses (block 128) ----
__global__ __launch_bounds__(256) void k_scan(float* __restrict__ out) {
    const int t = threadIdx.x;
    __shared__ int   ired[256];
    __shared__ float fred[256];

    if (blockIdx.x < 128) {
        const int b = blockIdx.x;      // bin
        __shared__ int wsum[8];
        __shared__ int woff[8];
        int c = g_counts[t * 128 + b];
        int v = c;
#pragma unroll
        for (int d = 1; d < 32; d <<= 1) {
            int u = __shfl_up_sync(0xffffffffu, v, d);
            if ((t & 31) >= d) v += u;
        }
        if ((t & 31) == 31) wsum[t >> 5] = v;
        __syncthreads();
        if (t == 0) {
            int run = 0;
#pragma unroll
            for (int i = 0; i < 8; i++) { woff[i] = run; run += wsum[i]; }
        }
        __syncthreads();
        g_off[t * 128 + b] = v + woff[t >> 5] - c;   // exclusive
        return;
    }

    // losses block
    {
        int e = t >> 2, q = t & 3;
        int csum = 0;
        for (int blk = q * 64; blk < q * 64 + 64; blk++)
            csum += g_counts[blk * 128 + e];          // top-1 bins are 0..63
        float msum = 0.f;
        for (int blk = q * 32; blk < q * 32 + 32; blk++)
            msum += g_mepart[blk * 64 + e];
        ired[t] = csum;
        fred[t] = msum;
    }
    __syncthreads();
    float a = 0.f;
    if (t < 64) {
        float me = (fred[4*t] + fred[4*t+1] + fred[4*t+2] + fred[4*t+3]) * (1.f / (float)N_TOK);
        float ce = (float)(ired[4*t] + ired[4*t+1] + ired[4*t+2] + ired[4*t+3]) * (1.f / (float)N_TOK);
        a = (float)E_DIM * me * ce;
    }
    __syncthreads();
    fred[t] = (t < 64) ? a : 0.f;
    __syncthreads();
    for (int s = 128; s > 0; s >>= 1) {
        if (t < s) fred[t] += fred[t + s];
        __syncthreads();
    }
    if (t == 0) out[AUX_OFF] = fred[0];
    __syncthreads();

    fred[t] = (t < NCTA_MAIN) ? g_zpart[t] : 0.f;
    __syncthreads();
    for (int s = 128; s > 0; s >>= 1) {
        if (t < s) fred[t] += fred[t + s];
        __syncthreads();
    }
    if (t == 0) out[Z_OFF] = fred[0] * (1.f / ((float)N_TOK * (float)E_DIM));
}

// ---------------- K3: scatter-only (output pre-zeroed by k_main) -----------
// 64 CTAs x 256 threads; one thread per token; <=4 scattered stores.
__global__ __launch_bounds__(256) void k_out(float* __restrict__ out) {
    const int n = blockIdx.x * 256 + threadIdx.x;   // token 0..16383

    uint32_t ii = g_t2i[n];
    int e1 = ii & 0xff, e2 = (ii >> 8) & 0xff;
    uint32_t rr = g_rank[n];
    float2 vv = g_t2v[n];
    int blk64 = n >> 6;

    int pos0 = g_off[blk64 * 128 + e1]      + (int)(rr & 0xffff);
    int pos1 = g_off[blk64 * 128 + 64 + e2] + (int)(rr >> 16);

    size_t base = (size_t)n * 128;
    if (pos0 < CAP) {
        out[DISP_OFF + base + e1 * 2 + 0] = 1.0f;
        out[COMB_OFF + base + e1 * 2 + 0] = vv.x;
    }
    if (pos1 < CAP) {
        out[DISP_OFF + base + e2 * 2 + 1] = 1.0f;
        out[COMB_OFF + base + e2 * 2 + 1] = vv.y;
    }
}

// ---------------- entry ----------------
extern "C" void kernel_launch(void* const* d_in, const int* in_sizes, int n_in,
                              void* d_out, int out_size) {
    const float* x = (const float*)d_in[0];   // [16384, 2048]
    const float* W = (const float*)d_in[1];   // [64, 2048]
    float* out = (float*)d_out;

    cudaFuncSetAttribute(k_main, cudaFuncAttributeMaxDynamicSharedMemorySize, SMEM_DYN);

    k_wsplit<<<(E_DIM * C_DIM) / 2048, 256>>>(W);   // 64 CTAs (512 float4 each)
    k_main<<<NCTA_MAIN, 256, SMEM_DYN>>>(x, out);
    k_scan<<<129, 256>>>(out);
    k_out<<<N_TOK / 256, 256>>>(out);
}

// round 16
// speedup vs baseline: 1.0979x; 1.0228x over previous
#include <cuda_runtime.h>
#include <cuda_fp16.h>
#include <cstdint>

// Problem constants
#define N_TOK 16384
#define C_DIM 2048
#define E_DIM 64
#define CAP   640                 // int(1.25 * 16384 * 2 / 64)

#define TOK_CTA   128             // tokens per k_main CTA
#define NCTA_MAIN (N_TOK / TOK_CTA)   // 128
#define KT        32              // K-tile (2 x k16 mma steps)
#define NTILE     (C_DIM / KT)    // 64
#define NBLK64    256             // 64-token blocks (rank/scan granularity)

#define XSTR 40                   // xs row stride (floats)
#define BSTR 40                   // W tile row stride (halves)
#define GSTR 66                   // logits row stride (floats)

#define XS_BYTES (TOK_CTA * XSTR * 4)     // 20480
#define WH_BYTES (E_DIM * BSTR * 2)       // 5120
#define STAGE_B  (XS_BYTES + 2 * WH_BYTES)    // 30720
#define SMEM_DYN (2 * STAGE_B)                // 61440

#define INV1024 0.0009765625f

// Output layout (float32)
#define DISP_OFF  ((size_t)0)
#define COMB_OFF  ((size_t)N_TOK * E_DIM * 2)
#define AUX_OFF   ((size_t)2 * N_TOK * E_DIM * 2)
#define Z_OFF     (AUX_OFF + 1)

// ---------------- scratch (static device globals; no allocs) ----------------
__device__ __half   g_Whh[E_DIM * C_DIM];   // fp16 hi part of W [e][k]
__device__ __half   g_Whl[E_DIM * C_DIM];   // fp16 (lo part * 1024)
__device__ uint32_t g_t2i[N_TOK];           // e1 | e2<<8
__device__ float2   g_t2v[N_TOK];           // top2 gate values
__device__ uint32_t g_rank[N_TOK];          // local rank: r0 | r1<<16
__device__ int      g_counts[NBLK64 * 128]; // per-64tok-block bin counts
__device__ int      g_off[NBLK64 * 128];    // exclusive scan across blocks
__device__ float    g_mepart[NCTA_MAIN * E_DIM];
__device__ float    g_zpart[NCTA_MAIN];

// ---------------- helpers ----------------
__device__ __forceinline__ uint32_t smem_u32(const void* p) {
    return (uint32_t)__cvta_generic_to_shared(p);
}
__device__ __forceinline__ void cpa16(uint32_t dst, const void* src) {
    asm volatile("cp.async.cg.shared.global [%0], [%1], 16;"
                 :: "r"(dst), "l"(src) : "memory");
}
__device__ __forceinline__ void mma16(float* d,
                                      uint32_t a0, uint32_t a1, uint32_t a2, uint32_t a3,
                                      uint32_t b0, uint32_t b1) {
    asm volatile(
        "mma.sync.aligned.m16n8k16.row.col.f32.f16.f16.f32 "
        "{%0,%1,%2,%3}, {%4,%5,%6,%7}, {%8,%9}, {%0,%1,%2,%3};"
        : "+f"(d[0]), "+f"(d[1]), "+f"(d[2]), "+f"(d[3])
        : "r"(a0), "r"(a1), "r"(a2), "r"(a3), "r"(b0), "r"(b1));
}
__device__ __forceinline__ void split2(float2 v, uint32_t& h, uint32_t& l) {
    __half2 hh = __floats2half2_rn(v.x, v.y);
    float2 hf = __half22float2(hh);
    __half2 ll = __floats2half2_rn(v.x - hf.x, v.y - hf.y);
    h = *(uint32_t*)&hh;
    l = *(uint32_t*)&ll;
}

// ---------------- K0: split W into fp16 hi / (lo*1024), vectorized ---------
// 64 CTAs x 256 threads; each thread handles 2 float4s (512 float4 per CTA).
__global__ __launch_bounds__(256) void k_wsplit(const float* __restrict__ W) {
    int base = blockIdx.x * 512 + threadIdx.x;   // float4 index space (32768)
    const float4* W4 = (const float4*)W;
    uint2* H2 = (uint2*)g_Whh;
    uint2* L2 = (uint2*)g_Whl;
#pragma unroll
    for (int r = 0; r < 2; r++) {
        int i = base + r * 256;
        float4 v = W4[i];
        __half2 h0 = __floats2half2_rn(v.x, v.y);
        __half2 h1 = __floats2half2_rn(v.z, v.w);
        float2 f0 = __half22float2(h0);
        float2 f1 = __half22float2(h1);
        __half2 l0 = __floats2half2_rn((v.x - f0.x) * 1024.f, (v.y - f0.y) * 1024.f);
        __half2 l1 = __floats2half2_rn((v.z - f1.x) * 1024.f, (v.w - f1.y) * 1024.f);
        H2[i] = make_uint2(*(uint32_t*)&h0, *(uint32_t*)&h1);
        L2[i] = make_uint2(*(uint32_t*)&l0, *(uint32_t*)&l1);
    }
}

// ---------------- K1: mma.sync fp16-split GEMM + softmax + top2 + ranks ----
// 256 threads (8 warps). Warp w: tokens [w*16, w*16+16), all 64 experts.
// 8 n-tiles of m16n8k16; accM = (xh+xl)*wh, accL = xh*(wl*1024).
__global__ __launch_bounds__(256) void k_main(const float* __restrict__ x) {
    extern __shared__ __align__(16) char smc[];
    __shared__ int   cnt[512];          // [half][warp_in_half][128 bins]
    __shared__ float sinv_s[TOK_CTA];
    __shared__ float redz[4];

    const int tid  = threadIdx.x;
    const int lane = tid & 31;
    const int w    = tid >> 5;
    const int cta  = blockIdx.x;
    const uint32_t smb = smem_u32(smc);
    const float* xbase = x + (size_t)cta * TOK_CTA * C_DIM;

#define LOAD_TILE(t) do {                                                     \
    uint32_t sb_ = smb + ((t) & 1) * STAGE_B;                                 \
    const float* xs_ = xbase + (t) * KT;                                      \
    _Pragma("unroll")                                                         \
    for (int c = tid; c < 1024; c += 256) {                                   \
        int row_ = c >> 3, seg_ = c & 7;                                      \
        cpa16(sb_ + (uint32_t)(row_ * (XSTR * 4) + seg_ * 16),                \
              xs_ + (size_t)row_ * C_DIM + seg_ * 4);                         \
    }                                                                         \
    {                                                                         \
        int row_ = tid >> 2, seg_ = tid & 3;                                  \
        const __half* wh_ = g_Whh + (size_t)row_ * C_DIM + (t) * KT + seg_ * 8;\
        const __half* wl_ = g_Whl + (size_t)row_ * C_DIM + (t) * KT + seg_ * 8;\
        cpa16(sb_ + XS_BYTES + (uint32_t)(row_ * (BSTR * 2) + seg_ * 16), wh_);\
        cpa16(sb_ + XS_BYTES + WH_BYTES + (uint32_t)(row_ * (BSTR * 2) + seg_ * 16), wl_);\
    }                                                                         \
} while (0)

    float accM[8][4], accL[8][4];
#pragma unroll
    for (int j = 0; j < 8; j++)
#pragma unroll
        for (int q = 0; q < 4; q++) { accM[j][q] = 0.f; accL[j][q] = 0.f; }

    const int tb = w * 16;
    const int tr = lane >> 2, tc = lane & 3;

    LOAD_TILE(0);
    asm volatile("cp.async.commit_group;" ::: "memory");

    for (int t = 0; t < NTILE; t++) {
        if (t + 1 < NTILE) LOAD_TILE(t + 1);
        asm volatile("cp.async.commit_group;" ::: "memory");
        asm volatile("cp.async.wait_group 1;" ::: "memory");
        __syncthreads();

        const char* st = smc + (t & 1) * STAGE_B;
        const float* xsA = (const float*)st + (tb + tr) * XSTR + 2 * tc;
        const __half* whB = (const __half*)(st + XS_BYTES) + tr * BSTR + 2 * tc;
        const __half* wlB = (const __half*)(st + XS_BYTES + WH_BYTES) + tr * BSTR + 2 * tc;

#pragma unroll
        for (int kk = 0; kk < KT; kk += 16) {
            float2 v0 = *(const float2*)(xsA + kk);
            float2 v1 = *(const float2*)(xsA + 8 * XSTR + kk);
            float2 v2 = *(const float2*)(xsA + kk + 8);
            float2 v3 = *(const float2*)(xsA + 8 * XSTR + kk + 8);
            uint32_t ah0, al0, ah1, al1, ah2, al2, ah3, al3;
            split2(v0, ah0, al0);
            split2(v1, ah1, al1);
            split2(v2, ah2, al2);
            split2(v3, ah3, al3);

#pragma unroll
            for (int j = 0; j < 8; j++) {
                const __half* whj = whB + j * 8 * BSTR + kk;
                const __half* wlj = wlB + j * 8 * BSTR + kk;
                uint32_t bh0 = *(const uint32_t*)whj;
                uint32_t bh1 = *(const uint32_t*)(whj + 8);
                uint32_t bl0 = *(const uint32_t*)wlj;
                uint32_t bl1 = *(const uint32_t*)(wlj + 8);
                mma16(accM[j], ah0, ah1, ah2, ah3, bh0, bh1);
                mma16(accM[j], al0, al1, al2, al3, bh0, bh1);
                mma16(accL[j], ah0, ah1, ah2, ah3, bl0, bl1);
            }
        }
        __syncthreads();   // protect buffer t&1 before iter t+1 prefetches t+2
    }

    // ---- combine + store logits to smem (stage0 reuse), stride GSTR ----
    float* gsm = (float*)smc;
    __syncthreads();
#pragma unroll
    for (int j = 0; j < 8; j++) {
        float l0 = accM[j][0] + accL[j][0] * INV1024;
        float l1 = accM[j][1] + accL[j][1] * INV1024;
        float l2 = accM[j][2] + accL[j][2] * INV1024;
        float l3 = accM[j][3] + accL[j][3] * INV1024;
        *(float2*)(gsm + (tb + tr) * GSTR + j * 8 + tc * 2) = make_float2(l0, l1);
        *(float2*)(gsm + (tb + tr + 8) * GSTR + j * 8 + tc * 2) = make_float2(l2, l3);
    }
    cnt[tid] = 0;
    cnt[tid + 256] = 0;
    __syncthreads();

    // ---- per-token softmax + top2 (threads 0..127, one token each) ----
    int i1 = 0, i2 = 0, r0 = 0, r1 = 0;
    float zsum = 0.f;
    if (w < 4) {
        float* row = gsm + tid * GSTR;
        float m = row[0];
#pragma unroll 4
        for (int e = 1; e < E_DIM; e++) m = fmaxf(m, row[e]);
        float s = 0.f, b1 = -1.f, b2 = -1.f;
#pragma unroll 4
        for (int e = 0; e < E_DIM; e++) {
            float l = row[e];
            zsum += l * l;
            float v = expf(l - m);
            row[e] = v;            // overwrite with unnormalized gate
            s += v;
            if (v > b1)      { b2 = b1; i2 = i1; b1 = v; i1 = e; }
            else if (v > b2) { b2 = v; i2 = e; }
        }
        float sinv = 1.f / s;
        sinv_s[tid] = sinv;
        int n = cta * TOK_CTA + tid;
        g_t2v[n] = make_float2(b1 * sinv, b2 * sinv);

        // deterministic local ranks (token order) within each 64-token half
        int half = w >> 1, wih = w & 1;
        unsigned lt = (1u << lane) - 1u;
        unsigned m0 = __match_any_sync(0xffffffffu, i1);
        r0 = __popc(m0 & lt);
        if ((m0 & lt) == 0) cnt[half * 256 + wih * 128 + i1] = __popc(m0);
        unsigned m1 = __match_any_sync(0xffffffffu, i2);
        r1 = __popc(m1 & lt);
        if ((m1 & lt) == 0) cnt[half * 256 + wih * 128 + 64 + i2] = __popc(m1);
    }
    // z reduce (warps 4..7 contribute zeros)
#pragma unroll
    for (int o = 16; o > 0; o >>= 1) zsum += __shfl_xor_sync(0xffffffffu, zsum, o);
    if (w < 4 && lane == 0) redz[w] = zsum;
    __syncthreads();

    if (w < 4) {
        int half = w >> 1;
        if ((w & 1) == 1) {               // second warp of half adds first warp's counts
            r0 += cnt[half * 256 + i1];
            r1 += cnt[half * 256 + 64 + i2];
        }
        int n = cta * TOK_CTA + tid;
        g_rank[n] = (uint32_t)r0 | ((uint32_t)r1 << 16);
        g_t2i[n]  = (uint32_t)i1 | ((uint32_t)i2 << 8);
    }
    {   // per-64tok-block bin counts (tid covers 256 = 2 halves x 128 bins)
        int half = tid >> 7, b = tid & 127;
        g_counts[(cta * 2 + half) * 128 + b] =
            cnt[half * 256 + b] + cnt[half * 256 + 128 + b];
    }
    if (tid < 64) {
        float sme = 0.f;
        for (int tok = 0; tok < TOK_CTA; tok++)
            sme += gsm[tok * GSTR + tid] * sinv_s[tok];
        g_mepart[cta * 64 + tid] = sme;
    }
    if (tid == 0)
        g_zpart[cta] = redz[0] + redz[1] + redz[2] + redz[3];
#undef LOAD_TILE
}

// ---------------- K2: per-bin scan (blocks 0..127) + losses (block 128) ----
__global__ __launch_bounds__(256) void k_scan(float* __restrict__ out) {
    const int t = threadIdx.x;
    __shared__ int   ired[256];
    __shared__ float fred[256];

    if (blockIdx.x < 128) {
        const int b = blockIdx.x;      // bin
        __shared__ int wsum[8];
        __shared__ int woff[8];
        int c = g_counts[t * 128 + b];
        int v = c;
#pragma unroll
        for (int d = 1; d < 32; d <<= 1) {
            int u = __shfl_up_sync(0xffffffffu, v, d);
            if ((t & 31) >= d) v += u;
        }
        if ((t & 31) == 31) wsum[t >> 5] = v;
        __syncthreads();
        if (t == 0) {
            int run = 0;
#pragma unroll
            for (int i = 0; i < 8; i++) { woff[i] = run; run += wsum[i]; }
        }
        __syncthreads();
        g_off[t * 128 + b] = v + woff[t >> 5] - c;   // exclusive
        return;
    }

    // losses block
    {
        int e = t >> 2, q = t & 3;
        int csum = 0;
        for (int blk = q * 64; blk < q * 64 + 64; blk++)
            csum += g_counts[blk * 128 + e];          // top-1 bins are 0..63
        float msum = 0.f;
        for (int blk = q * 32; blk < q * 32 + 32; blk++)
            msum += g_mepart[blk * 64 + e];
        ired[t] = csum;
        fred[t] = msum;
    }
    __syncthreads();
    float a = 0.f;
    if (t < 64) {
        float me = (fred[4*t] + fred[4*t+1] + fred[4*t+2] + fred[4*t+3]) * (1.f / (float)N_TOK);
        float ce = (float)(ired[4*t] + ired[4*t+1] + ired[4*t+2] + ired[4*t+3]) * (1.f / (float)N_TOK);
        a = (float)E_DIM * me * ce;
    }
    __syncthreads();
    fred[t] = (t < 64) ? a : 0.f;
    __syncthreads();
    for (int s = 128; s > 0; s >>= 1) {
        if (t < s) fred[t] += fred[t + s];
        __syncthreads();
    }
    if (t == 0) out[AUX_OFF] = fred[0];
    __syncthreads();

    fred[t] = (t < NCTA_MAIN) ? g_zpart[t] : 0.f;
    __syncthreads();
    for (int s = 128; s > 0; s >>= 1) {
        if (t < s) fred[t] += fred[t + s];
        __syncthreads();
    }
    if (t == 0) out[Z_OFF] = fred[0] * (1.f / ((float)N_TOK * (float)E_DIM));
}

// ---------------- K3: zero + scatter outputs (1024 CTAs x 16 tokens) -------
__global__ __launch_bounds__(256) void k_out(float* __restrict__ out) {
    const int cta = blockIdx.x;
    const int tid = threadIdx.x;

    float4 z4 = make_float4(0.f, 0.f, 0.f, 0.f);
    float4* dz = (float4*)(out + DISP_OFF + (size_t)cta * 16 * 128);
    float4* cz = (float4*)(out + COMB_OFF + (size_t)cta * 16 * 128);
#pragma unroll
    for (int i = 0; i < 2; i++) {
        dz[tid + i * 256] = z4;
        cz[tid + i * 256] = z4;
    }
    __syncthreads();

    if (tid < 16) {
        int n = cta * 16 + tid;
        uint32_t ii = g_t2i[n];
        int e1 = ii & 0xff, e2 = (ii >> 8) & 0xff;
        uint32_t rr = g_rank[n];
        float2 vv = g_t2v[n];
        int blk64 = n >> 6;

        int pos0 = g_off[blk64 * 128 + e1]      + (int)(rr & 0xffff);
        int pos1 = g_off[blk64 * 128 + 64 + e2] + (int)(rr >> 16);

        size_t base = (size_t)n * 128;
        if (pos0 < CAP) {
            out[DISP_OFF + base + e1 * 2 + 0] = 1.0f;
            out[COMB_OFF + base + e1 * 2 + 0] = vv.x;
        }
        if (pos1 < CAP) {
            out[DISP_OFF + base + e2 * 2 + 1] = 1.0f;
            out[COMB_OFF + base + e2 * 2 + 1] = vv.y;
        }
    }
}

// ---------------- entry ----------------
extern "C" void kernel_launch(void* const* d_in, const int* in_sizes, int n_in,
                              void* d_out, int out_size) {
    const float* x = (const float*)d_in[0];   // [16384, 2048]
    const float* W = (const float*)d_in[1];   // [64, 2048]
    float* out = (float*)d_out;

    cudaFuncSetAttribute(k_main, cudaFuncAttributeMaxDynamicSharedMemorySize, SMEM_DYN);

    k_wsplit<<<(E_DIM * C_DIM) / 2048, 256>>>(W);   // 64 CTAs (512 float4 each)
    k_main<<<NCTA_MAIN, 256, SMEM_DYN>>>(x);
    k_scan<<<129, 256>>>(out);
    k_out<<<1024, 256>>>(out);
}